// round 5
// baseline (speedup 1.0000x reference)
#include <cuda_runtime.h>
#include <cuda_bf16.h>
#include <cstdint>

#define GCNT   16384
#define NNODE  17
#define CH     128
#define NEDGE  81
#define TT     64
#define BB     256
#define G4     512
#define LSTMIN 2176
#define NCLS   10
#define MROWS  (GCNT * NNODE)   // 278528

// ---------------- static device scratch ----------------
__device__ float g_bufA[(size_t)GCNT * NNODE * CH];
__device__ float g_bufB[(size_t)GCNT * NNODE * CH];
__device__ float g_x0[(size_t)GCNT * G4];
__device__ float g_x1[(size_t)GCNT * G4];
__device__ float g_hs1[(size_t)BB * TT * CH];
__device__ float g_hs2[(size_t)BB * TT * CH];
__device__ float g_whhT0[CH * G4];
__device__ float g_whhT1[CH * G4];
__device__ float g_wt[3][CH * CH];
__device__ int g_src[NEDGE], g_dst[NEDGE], g_csr[NEDGE], g_start[NNODE + 1];

// ---------------- setup: edge CSR (same for every graph) ----------------
__global__ void setup_kernel(const int* __restrict__ eidx) {
    if (threadIdx.x == 0) {
        for (int e = 0; e < 64; e++) { g_src[e] = eidx[e]; g_dst[e] = eidx[64 + e]; }
        for (int n = 0; n < NNODE; n++) { g_src[64 + n] = n; g_dst[64 + n] = n; }
        int pos = 0;
        for (int n = 0; n < NNODE; n++) {
            g_start[n] = pos;
            for (int e = 0; e < NEDGE; e++)
                if (g_dst[e] == n) g_csr[pos++] = e;
        }
        g_start[NNODE] = pos;
    }
}

// whh [512,128] -> whhT [128,512] (k-major rows, gate-row contiguous)
__global__ void transpose_whh(const float* __restrict__ whh, float* __restrict__ out) {
    int i = blockIdx.x * 256 + threadIdx.x;
    if (i < G4 * CH) {
        int r = i / CH, k = i % CH;
        out[k * G4 + r] = whh[i];
    }
}

// W [128(k),128(n)] -> Wt [128(n),128(k)]
__global__ void transpose128(const float* __restrict__ W, float* __restrict__ Wt) {
    int i = blockIdx.x * 256 + threadIdx.x;   // 16384
    if (i < CH * CH) {
        int k = i >> 7, n = i & 127;
        Wt[n * CH + k] = W[i];
    }
}

// ---------------- fused GAT layer 0 (CIN=3): one block per graph ----------------
template <int CIN, bool RELU>
__global__ __launch_bounds__(128) void gat_kernel(
    const float* __restrict__ in, const float* __restrict__ W,
    const float* __restrict__ a_src, const float* __restrict__ a_dst,
    const float* __restrict__ bias, float* __restrict__ out)
{
    __shared__ __align__(16) float sIn[NNODE * CIN];
    __shared__ __align__(16) float sH[NNODE * CH];
    __shared__ float sAtt[2 * CH];
    __shared__ float sAS[NNODE * 2], sAD[NNODE * 2];
    __shared__ float sM[NNODE * 2], sDen[NNODE * 2];
    __shared__ float sAlpha[NEDGE * 2];
    __shared__ int sStart[NNODE + 1];
    __shared__ int sCsr[NEDGE], sSrc[NEDGE], sDst[NEDGE];

    const int g = blockIdx.x, tid = threadIdx.x;

    for (int i = tid; i < NNODE * CIN; i += 128)
        sIn[i] = in[(size_t)g * (NNODE * CIN) + i];
    sAtt[tid]      = a_src[tid];
    sAtt[CH + tid] = a_dst[tid];
    if (tid <= NNODE) sStart[tid] = g_start[tid];
    if (tid < NEDGE) { sCsr[tid] = g_csr[tid]; sSrc[tid] = g_src[tid]; sDst[tid] = g_dst[tid]; }
    __syncthreads();

    float acc[NNODE];
#pragma unroll
    for (int n = 0; n < NNODE; n++) acc[n] = 0.f;
#pragma unroll
    for (int k = 0; k < CIN; k++) {
        float w = W[k * CH + tid];
#pragma unroll
        for (int n = 0; n < NNODE; n++) acc[n] = fmaf(sIn[n * CIN + k], w, acc[n]);
    }
#pragma unroll
    for (int n = 0; n < NNODE; n++) sH[n * CH + tid] = acc[n];
    __syncthreads();

    if (tid < NNODE * 2) {
        int n = tid >> 1, hh = tid & 1;
        float s = 0.f, d = 0.f;
        const float* hrow = &sH[n * CH + hh * 64];
#pragma unroll 8
        for (int k = 0; k < 64; k++) {
            float hv = hrow[k];
            s = fmaf(hv, sAtt[hh * 64 + k], s);
            d = fmaf(hv, sAtt[CH + hh * 64 + k], d);
        }
        sAS[tid] = s; sAD[tid] = d;
    }
    __syncthreads();

    if (tid < NNODE * 2) {
        int n = tid >> 1, hh = tid & 1;
        float ad = sAD[n * 2 + hh];
        int s0 = sStart[n], s1 = sStart[n + 1];
        float m = -1e30f;
        for (int p = s0; p < s1; p++) {
            float v = sAS[sSrc[sCsr[p]] * 2 + hh] + ad;
            v = v > 0.f ? v : 0.2f * v;
            m = fmaxf(m, v);
        }
        float den = 0.f;
        for (int p = s0; p < s1; p++) {
            float v = sAS[sSrc[sCsr[p]] * 2 + hh] + ad;
            v = v > 0.f ? v : 0.2f * v;
            den += expf(v - m);
        }
        sM[tid] = m; sDen[tid] = den;
    }
    __syncthreads();

    for (int i = tid; i < NEDGE * 2; i += 128) {
        int e = i >> 1, hh = i & 1;
        int s = sSrc[e], d = sDst[e];
        float v = sAS[s * 2 + hh] + sAD[d * 2 + hh];
        v = v > 0.f ? v : 0.2f * v;
        sAlpha[i] = expf(v - sM[d * 2 + hh]) / (sDen[d * 2 + hh] + 1e-16f);
    }
    __syncthreads();

    const float bv = bias[tid];
    const int hh = tid >> 6;
    for (int n = 0; n < NNODE; n++) {
        float o = bv;
        int s0 = sStart[n], s1 = sStart[n + 1];
        for (int p = s0; p < s1; p++) {
            int e = sCsr[p];
            o = fmaf(sAlpha[e * 2 + hh], sH[sSrc[e] * CH + tid], o);
        }
        if (RELU) o = fmaxf(o, 0.f);
        out[(size_t)g * (NNODE * CH) + n * CH + tid] = o;
    }
}

// ---------------- GAT epilogue (after GEMM): one block per graph ----------------
template <bool RELU>
__global__ __launch_bounds__(128) void gat_epilogue(
    const float* __restrict__ hbuf,    // [G,17,128] = in @ W
    const float* __restrict__ a_src, const float* __restrict__ a_dst,
    const float* __restrict__ bias, float* __restrict__ out)
{
    __shared__ __align__(16) float sH[NNODE * CH];
    __shared__ float sAtt[2 * CH];
    __shared__ float sAS[NNODE * 2], sAD[NNODE * 2];
    __shared__ float sM[NNODE * 2], sDen[NNODE * 2];
    __shared__ float sAlpha[NEDGE * 2];
    __shared__ int sStart[NNODE + 1];
    __shared__ int sCsr[NEDGE], sSrc[NEDGE], sDst[NEDGE];

    const int g = blockIdx.x, tid = threadIdx.x;
    const float4* src4 = (const float4*)(hbuf + (size_t)g * (NNODE * CH));
    float4* sH4 = (float4*)sH;
    for (int i = tid; i < NNODE * CH / 4; i += 128) sH4[i] = src4[i];
    sAtt[tid]      = a_src[tid];
    sAtt[CH + tid] = a_dst[tid];
    if (tid <= NNODE) sStart[tid] = g_start[tid];
    if (tid < NEDGE) { sCsr[tid] = g_csr[tid]; sSrc[tid] = g_src[tid]; sDst[tid] = g_dst[tid]; }
    __syncthreads();

    if (tid < NNODE * 2) {
        int n = tid >> 1, hh = tid & 1;
        float s = 0.f, d = 0.f;
        const float* hrow = &sH[n * CH + hh * 64];
#pragma unroll 8
        for (int k = 0; k < 64; k++) {
            float hv = hrow[k];
            s = fmaf(hv, sAtt[hh * 64 + k], s);
            d = fmaf(hv, sAtt[CH + hh * 64 + k], d);
        }
        sAS[tid] = s; sAD[tid] = d;
    }
    __syncthreads();

    if (tid < NNODE * 2) {
        int n = tid >> 1, hh = tid & 1;
        float ad = sAD[n * 2 + hh];
        int s0 = sStart[n], s1 = sStart[n + 1];
        float m = -1e30f;
        for (int p = s0; p < s1; p++) {
            float v = sAS[sSrc[sCsr[p]] * 2 + hh] + ad;
            v = v > 0.f ? v : 0.2f * v;
            m = fmaxf(m, v);
        }
        float den = 0.f;
        for (int p = s0; p < s1; p++) {
            float v = sAS[sSrc[sCsr[p]] * 2 + hh] + ad;
            v = v > 0.f ? v : 0.2f * v;
            den += expf(v - m);
        }
        sM[tid] = m; sDen[tid] = den;
    }
    __syncthreads();

    for (int i = tid; i < NEDGE * 2; i += 128) {
        int e = i >> 1, hh = i & 1;
        int s = sSrc[e], d = sDst[e];
        float v = sAS[s * 2 + hh] + sAD[d * 2 + hh];
        v = v > 0.f ? v : 0.2f * v;
        sAlpha[i] = expf(v - sM[d * 2 + hh]) / (sDen[d * 2 + hh] + 1e-16f);
    }
    __syncthreads();

    const float bv = bias[tid];
    const int hh = tid >> 6;
    for (int n = 0; n < NNODE; n++) {
        float o = bv;
        int s0 = sStart[n], s1 = sStart[n + 1];
        for (int p = s0; p < s1; p++) {
            int e = sCsr[p];
            o = fmaf(sAlpha[e * 2 + hh], sH[sSrc[e] * CH + tid], o);
        }
        if (RELU) o = fmaxf(o, 0.f);
        out[(size_t)g * (NNODE * CH) + n * CH + tid] = o;
    }
}

// ---------------- double-buffered SGEMM NT: C = A[M,K]*B[N,K]^T (+ b0 + b1) ----------------
__global__ __launch_bounds__(256) void sgemm_nt(
    const float* __restrict__ A, const float* __restrict__ Bm,
    const float* __restrict__ b0, const float* __restrict__ b1,
    float* __restrict__ Cm, int M, int N, int K)
{
    __shared__ __align__(16) float sA[2][16][128];
    __shared__ __align__(16) float sB[2][16][128];
    const int tid = threadIdx.x;
    const int bm = blockIdx.y * 128, bn = blockIdx.x * 128;
    const int tx = tid & 15, ty = tid >> 4;
    const int lr0 = tid >> 2,         lk0 = tid & 3;
    const int lr1 = (tid + 256) >> 2, lk1 = (tid + 256) & 3;

    float acc[8][8] = {};
    float4 ra0, ra1, rb0, rb1;

    ra0 = *(const float4*)&A[(size_t)(bm + lr0) * K + lk0 * 4];
    ra1 = *(const float4*)&A[(size_t)(bm + lr1) * K + lk1 * 4];
    rb0 = *(const float4*)&Bm[(size_t)(bn + lr0) * K + lk0 * 4];
    rb1 = *(const float4*)&Bm[(size_t)(bn + lr1) * K + lk1 * 4];
    sA[0][lk0 * 4 + 0][lr0] = ra0.x; sA[0][lk0 * 4 + 1][lr0] = ra0.y;
    sA[0][lk0 * 4 + 2][lr0] = ra0.z; sA[0][lk0 * 4 + 3][lr0] = ra0.w;
    sA[0][lk1 * 4 + 0][lr1] = ra1.x; sA[0][lk1 * 4 + 1][lr1] = ra1.y;
    sA[0][lk1 * 4 + 2][lr1] = ra1.z; sA[0][lk1 * 4 + 3][lr1] = ra1.w;
    sB[0][lk0 * 4 + 0][lr0] = rb0.x; sB[0][lk0 * 4 + 1][lr0] = rb0.y;
    sB[0][lk0 * 4 + 2][lr0] = rb0.z; sB[0][lk0 * 4 + 3][lr0] = rb0.w;
    sB[0][lk1 * 4 + 0][lr1] = rb1.x; sB[0][lk1 * 4 + 1][lr1] = rb1.y;
    sB[0][lk1 * 4 + 2][lr1] = rb1.z; sB[0][lk1 * 4 + 3][lr1] = rb1.w;
    __syncthreads();

    const int nk = K >> 4;
    for (int kt = 0; kt < nk; kt++) {
        const int cur = kt & 1, nxt = cur ^ 1;
        const bool more = (kt + 1 < nk);
        if (more) {
            int k0 = (kt + 1) << 4;
            ra0 = *(const float4*)&A[(size_t)(bm + lr0) * K + k0 + lk0 * 4];
            ra1 = *(const float4*)&A[(size_t)(bm + lr1) * K + k0 + lk1 * 4];
            rb0 = *(const float4*)&Bm[(size_t)(bn + lr0) * K + k0 + lk0 * 4];
            rb1 = *(const float4*)&Bm[(size_t)(bn + lr1) * K + k0 + lk1 * 4];
        }
#pragma unroll
        for (int k = 0; k < 16; k++) {
            float a[8], b[8];
            *(float4*)&a[0] = *(const float4*)&sA[cur][k][ty * 8];
            *(float4*)&a[4] = *(const float4*)&sA[cur][k][ty * 8 + 4];
            *(float4*)&b[0] = *(const float4*)&sB[cur][k][tx * 8];
            *(float4*)&b[4] = *(const float4*)&sB[cur][k][tx * 8 + 4];
#pragma unroll
            for (int i = 0; i < 8; i++)
#pragma unroll
                for (int j = 0; j < 8; j++)
                    acc[i][j] = fmaf(a[i], b[j], acc[i][j]);
        }
        if (more) {
            sA[nxt][lk0 * 4 + 0][lr0] = ra0.x; sA[nxt][lk0 * 4 + 1][lr0] = ra0.y;
            sA[nxt][lk0 * 4 + 2][lr0] = ra0.z; sA[nxt][lk0 * 4 + 3][lr0] = ra0.w;
            sA[nxt][lk1 * 4 + 0][lr1] = ra1.x; sA[nxt][lk1 * 4 + 1][lr1] = ra1.y;
            sA[nxt][lk1 * 4 + 2][lr1] = ra1.z; sA[nxt][lk1 * 4 + 3][lr1] = ra1.w;
            sB[nxt][lk0 * 4 + 0][lr0] = rb0.x; sB[nxt][lk0 * 4 + 1][lr0] = rb0.y;
            sB[nxt][lk0 * 4 + 2][lr0] = rb0.z; sB[nxt][lk0 * 4 + 3][lr0] = rb0.w;
            sB[nxt][lk1 * 4 + 0][lr1] = rb1.x; sB[nxt][lk1 * 4 + 1][lr1] = rb1.y;
            sB[nxt][lk1 * 4 + 2][lr1] = rb1.z; sB[nxt][lk1 * 4 + 3][lr1] = rb1.w;
        }
        __syncthreads();
    }

    float bj[8];
#pragma unroll
    for (int j = 0; j < 8; j++) {
        int col = bn + tx * 8 + j;
        bj[j] = b0 ? (b0[col] + b1[col]) : 0.f;
    }
#pragma unroll
    for (int i = 0; i < 8; i++) {
        size_t row = (size_t)(bm + ty * 8 + i);
        float4 v0, v1;
        v0.x = acc[i][0] + bj[0]; v0.y = acc[i][1] + bj[1];
        v0.z = acc[i][2] + bj[2]; v0.w = acc[i][3] + bj[3];
        v1.x = acc[i][4] + bj[4]; v1.y = acc[i][5] + bj[5];
        v1.z = acc[i][6] + bj[6]; v1.w = acc[i][7] + bj[7];
        *(float4*)&Cm[row * N + bn + tx * 8]     = v0;
        *(float4*)&Cm[row * N + bn + tx * 8 + 4] = v1;
    }
}

// ---------------- LSTM recurrence: 8 batches/block, 32 blocks ----------------
__global__ __launch_bounds__(512) void lstm_kernel(
    const float* __restrict__ Xpre, const float* __restrict__ whhT,
    float* __restrict__ hs)
{
    __shared__ __align__(16) float sh[8][CH];
    __shared__ float sg[8][G4];
    const int tid = threadIdx.x;
    const int b0 = blockIdx.x * 8;
    const int u = tid & 127, bh = tid >> 7;

    for (int i = tid; i < 8 * CH; i += 512) ((float*)sh)[i] = 0.f;
    float c0 = 0.f, c1 = 0.f;
    __syncthreads();

    for (int t = 0; t < TT; t++) {
        float acc[8];
#pragma unroll
        for (int b = 0; b < 8; b++)
            acc[b] = Xpre[((size_t)(b0 + b) * TT + t) * G4 + tid];
#pragma unroll 4
        for (int k4 = 0; k4 < 32; k4++) {
            int k = k4 * 4;
            float w0 = whhT[(k + 0) * G4 + tid];
            float w1 = whhT[(k + 1) * G4 + tid];
            float w2 = whhT[(k + 2) * G4 + tid];
            float w3 = whhT[(k + 3) * G4 + tid];
#pragma unroll
            for (int b = 0; b < 8; b++) {
                float4 h = *(const float4*)&sh[b][k];
                acc[b] = fmaf(w3, h.w, fmaf(w2, h.z, fmaf(w1, h.y, fmaf(w0, h.x, acc[b]))));
            }
        }
#pragma unroll
        for (int b = 0; b < 8; b++) sg[b][tid] = acc[b];
        __syncthreads();

        {
            float gi = sg[bh][u],       gf = sg[bh][128 + u];
            float gg = sg[bh][256 + u], go = sg[bh][384 + u];
            float fi = 1.f / (1.f + expf(-gi));
            float ff = 1.f / (1.f + expf(-gf));
            float fo = 1.f / (1.f + expf(-go));
            c0 = ff * c0 + fi * tanhf(gg);
            float h = fo * tanhf(c0);
            sh[bh][u] = h;
            hs[((size_t)(b0 + bh) * TT + t) * CH + u] = h;
        }
        {
            int b = bh + 4;
            float gi = sg[b][u],       gf = sg[b][128 + u];
            float gg = sg[b][256 + u], go = sg[b][384 + u];
            float fi = 1.f / (1.f + expf(-gi));
            float ff = 1.f / (1.f + expf(-gf));
            float fo = 1.f / (1.f + expf(-go));
            c1 = ff * c1 + fi * tanhf(gg);
            float h = fo * tanhf(c1);
            sh[b][u] = h;
            hs[((size_t)(b0 + b) * TT + t) * CH + u] = h;
        }
        __syncthreads();
    }
}

// ---------------- attention + FC: one block per batch ----------------
__global__ __launch_bounds__(128) void attn_fc_kernel(
    const float* __restrict__ hs2, const float* __restrict__ attn_w,
    const float* __restrict__ attn_b, const float* __restrict__ fc_w,
    const float* __restrict__ fc_b, float* __restrict__ out)
{
    __shared__ float ssc[TT];
    __shared__ float sctx[CH];
    const int b = blockIdx.x, tid = threadIdx.x;

    if (tid < TT) {
        const float* hr = hs2 + ((size_t)b * TT + tid) * CH;
        float d = attn_b[0];
        for (int k = 0; k < CH; k++) d = fmaf(hr[k], attn_w[k], d);
        ssc[tid] = tanhf(d);
    }
    __syncthreads();
    if (tid == 0) {
        float m = -1e30f;
        for (int t = 0; t < TT; t++) m = fmaxf(m, ssc[t]);
        float s = 0.f;
        for (int t = 0; t < TT; t++) { float e = expf(ssc[t] - m); ssc[t] = e; s += e; }
        float inv = 1.f / s;
        for (int t = 0; t < TT; t++) ssc[t] *= inv;
    }
    __syncthreads();
    float cx = 0.f;
    for (int t = 0; t < TT; t++)
        cx = fmaf(ssc[t], hs2[((size_t)b * TT + t) * CH + tid], cx);
    sctx[tid] = cx;
    __syncthreads();
    if (tid < NCLS) {
        float o = fc_b[tid];
        for (int k = 0; k < CH; k++) o = fmaf(sctx[k], fc_w[tid * CH + k], o);
        out[b * NCLS + tid] = o;
    }
}

// ---------------- launch ----------------
extern "C" void kernel_launch(void* const* d_in, const int* in_sizes, int n_in,
                              void* d_out, int out_size) {
    const float* x     = (const float*)d_in[0];
    const int*   eidx  = (const int*)d_in[1];
    const float* gw[4], *gas[4], *gad[4], *gb[4];
    for (int i = 0; i < 4; i++) {
        gw[i]  = (const float*)d_in[2 + 4 * i];
        gas[i] = (const float*)d_in[3 + 4 * i];
        gad[i] = (const float*)d_in[4 + 4 * i];
        gb[i]  = (const float*)d_in[5 + 4 * i];
    }
    const float* wih0 = (const float*)d_in[18];
    const float* whh0 = (const float*)d_in[19];
    const float* bih0 = (const float*)d_in[20];
    const float* bhh0 = (const float*)d_in[21];
    const float* wih1 = (const float*)d_in[22];
    const float* whh1 = (const float*)d_in[23];
    const float* bih1 = (const float*)d_in[24];
    const float* bhh1 = (const float*)d_in[25];
    const float* attn_w = (const float*)d_in[26];
    const float* attn_b = (const float*)d_in[27];
    const float* fc_w   = (const float*)d_in[28];
    const float* fc_b   = (const float*)d_in[29];

    float *bufA, *bufB, *x0, *x1, *hs1, *hs2, *whhT0, *whhT1, *wt;
    cudaGetSymbolAddress((void**)&bufA,  g_bufA);
    cudaGetSymbolAddress((void**)&bufB,  g_bufB);
    cudaGetSymbolAddress((void**)&x0,    g_x0);
    cudaGetSymbolAddress((void**)&x1,    g_x1);
    cudaGetSymbolAddress((void**)&hs1,   g_hs1);
    cudaGetSymbolAddress((void**)&hs2,   g_hs2);
    cudaGetSymbolAddress((void**)&whhT0, g_whhT0);
    cudaGetSymbolAddress((void**)&whhT1, g_whhT1);
    cudaGetSymbolAddress((void**)&wt,    g_wt);

    setup_kernel<<<1, 32>>>(eidx);
    transpose_whh<<<256, 256>>>(whh0, whhT0);
    transpose_whh<<<256, 256>>>(whh1, whhT1);
    transpose128<<<64, 256>>>(gw[1], wt + 0 * CH * CH);
    transpose128<<<64, 256>>>(gw[2], wt + 1 * CH * CH);
    transpose128<<<64, 256>>>(gw[3], wt + 2 * CH * CH);

    // layer 0 fused (CIN=3, relu)
    gat_kernel<3, true><<<GCNT, 128>>>(x, gw[0], gas[0], gad[0], gb[0], bufA);

    // layers 1..3: GEMM (h = in @ W) + epilogue
    sgemm_nt<<<dim3(1, MROWS / 128), 256>>>(bufA, wt + 0 * CH * CH, nullptr, nullptr, bufB, MROWS, CH, CH);
    gat_epilogue<false><<<GCNT, 128>>>(bufB, gas[1], gad[1], gb[1], bufA);
    sgemm_nt<<<dim3(1, MROWS / 128), 256>>>(bufA, wt + 1 * CH * CH, nullptr, nullptr, bufB, MROWS, CH, CH);
    gat_epilogue<true><<<GCNT, 128>>>(bufB, gas[2], gad[2], gb[2], bufA);
    sgemm_nt<<<dim3(1, MROWS / 128), 256>>>(bufA, wt + 2 * CH * CH, nullptr, nullptr, bufB, MROWS, CH, CH);
    gat_epilogue<false><<<GCNT, 128>>>(bufB, gas[3], gad[3], gb[3], bufA);

    // LSTM stack
    sgemm_nt<<<dim3(4, 128), 256>>>(bufA, wih0, bih0, bhh0, x0, GCNT, G4, LSTMIN);
    lstm_kernel<<<32, 512>>>(x0, whhT0, hs1);
    sgemm_nt<<<dim3(4, 128), 256>>>(hs1, wih1, bih1, bhh1, x1, GCNT, G4, CH);
    lstm_kernel<<<32, 512>>>(x1, whhT1, hs2);

    attn_fc_kernel<<<BB, 128>>>(hs2, attn_w, attn_b, fc_w, fc_b, (float*)d_out);
}

// round 9
// speedup vs baseline: 1.2152x; 1.2152x over previous
#include <cuda_runtime.h>
#include <cuda_bf16.h>
#include <cstdint>

#define GCNT   16384
#define NNODE  17
#define CH     128
#define NEDGE  81
#define TT     64
#define BB     256
#define G4     512
#define LSTMIN 2176
#define NCLS   10

// ---------------- static device scratch ----------------
__device__ float g_bufA[(size_t)GCNT * NNODE * CH];
__device__ float g_bufB[(size_t)GCNT * NNODE * CH];
__device__ float g_x0[(size_t)GCNT * G4];
__device__ float g_x1[(size_t)GCNT * G4];
__device__ float g_hs1[(size_t)BB * TT * CH];
__device__ float g_hs2[(size_t)BB * TT * CH];
__device__ float g_whhT0[CH * G4];
__device__ float g_whhT1[CH * G4];
__device__ int g_src[NEDGE], g_dst[NEDGE], g_csr[NEDGE], g_start[NNODE + 1];

// ---------------- setup ----------------
__global__ void setup_kernel(const int* __restrict__ eidx) {
    if (threadIdx.x == 0) {
        for (int e = 0; e < 64; e++) { g_src[e] = eidx[e]; g_dst[e] = eidx[64 + e]; }
        for (int n = 0; n < NNODE; n++) { g_src[64 + n] = n; g_dst[64 + n] = n; }
        int pos = 0;
        for (int n = 0; n < NNODE; n++) {
            g_start[n] = pos;
            for (int e = 0; e < NEDGE; e++)
                if (g_dst[e] == n) g_csr[pos++] = e;
        }
        g_start[NNODE] = pos;
    }
}

__global__ void transpose_whh(const float* __restrict__ whh, float* __restrict__ out) {
    int i = blockIdx.x * 256 + threadIdx.x;
    if (i < G4 * CH) {
        int r = i / CH, k = i % CH;
        out[k * G4 + r] = whh[i];
    }
}

// ---------------- fused GAT layer: one block per graph, 128 threads (R1, measured 3058 config) ----------------
template <int CIN, bool RELU>
__global__ __launch_bounds__(128) void gat_kernel(
    const float* __restrict__ in, const float* __restrict__ W,
    const float* __restrict__ a_src, const float* __restrict__ a_dst,
    const float* __restrict__ bias, float* __restrict__ out)
{
    __shared__ __align__(16) float sIn[NNODE * CIN];
    __shared__ __align__(16) float sH[NNODE * CH];
    __shared__ float sAtt[2 * CH];
    __shared__ float sAS[NNODE * 2], sAD[NNODE * 2];
    __shared__ float sM[NNODE * 2], sDen[NNODE * 2];
    __shared__ float sAlpha[NEDGE * 2];
    __shared__ int sStart[NNODE + 1];
    __shared__ int sCsr[NEDGE], sSrc[NEDGE], sDst[NEDGE];

    const int g = blockIdx.x, tid = threadIdx.x;

    for (int i = tid; i < NNODE * CIN; i += 128)
        sIn[i] = in[(size_t)g * (NNODE * CIN) + i];
    sAtt[tid]      = a_src[tid];
    sAtt[CH + tid] = a_dst[tid];
    if (tid <= NNODE) sStart[tid] = g_start[tid];
    if (tid < NEDGE) { sCsr[tid] = g_csr[tid]; sSrc[tid] = g_src[tid]; sDst[tid] = g_dst[tid]; }
    __syncthreads();

    float acc[NNODE];
#pragma unroll
    for (int n = 0; n < NNODE; n++) acc[n] = 0.f;

    if constexpr ((CIN & 3) == 0) {
        for (int k0 = 0; k0 < CIN; k0 += 4) {
            float w0 = W[(k0 + 0) * CH + tid];
            float w1 = W[(k0 + 1) * CH + tid];
            float w2 = W[(k0 + 2) * CH + tid];
            float w3 = W[(k0 + 3) * CH + tid];
#pragma unroll
            for (int n = 0; n < NNODE; n++) {
                float4 xv = *(const float4*)&sIn[n * CIN + k0];
                acc[n] = fmaf(xv.w, w3, fmaf(xv.z, w2, fmaf(xv.y, w1, fmaf(xv.x, w0, acc[n]))));
            }
        }
    } else {
#pragma unroll
        for (int k = 0; k < CIN; k++) {
            float w = W[k * CH + tid];
#pragma unroll
            for (int n = 0; n < NNODE; n++) acc[n] = fmaf(sIn[n * CIN + k], w, acc[n]);
        }
    }
#pragma unroll
    for (int n = 0; n < NNODE; n++) sH[n * CH + tid] = acc[n];
    __syncthreads();

    if (tid < NNODE * 2) {
        int n = tid >> 1, hh = tid & 1;
        float s = 0.f, d = 0.f;
        const float* hrow = &sH[n * CH + hh * 64];
#pragma unroll 8
        for (int k = 0; k < 64; k++) {
            float hv = hrow[k];
            s = fmaf(hv, sAtt[hh * 64 + k], s);
            d = fmaf(hv, sAtt[CH + hh * 64 + k], d);
        }
        sAS[tid] = s; sAD[tid] = d;
    }
    __syncthreads();

    if (tid < NNODE * 2) {
        int n = tid >> 1, hh = tid & 1;
        float ad = sAD[n * 2 + hh];
        int s0 = sStart[n], s1 = sStart[n + 1];
        float m = -1e30f;
        for (int p = s0; p < s1; p++) {
            float v = sAS[sSrc[sCsr[p]] * 2 + hh] + ad;
            v = v > 0.f ? v : 0.2f * v;
            m = fmaxf(m, v);
        }
        float den = 0.f;
        for (int p = s0; p < s1; p++) {
            float v = sAS[sSrc[sCsr[p]] * 2 + hh] + ad;
            v = v > 0.f ? v : 0.2f * v;
            den += expf(v - m);
        }
        sM[tid] = m; sDen[tid] = den;
    }
    __syncthreads();

    for (int i = tid; i < NEDGE * 2; i += 128) {
        int e = i >> 1, hh = i & 1;
        int s = sSrc[e], d = sDst[e];
        float v = sAS[s * 2 + hh] + sAD[d * 2 + hh];
        v = v > 0.f ? v : 0.2f * v;
        sAlpha[i] = expf(v - sM[d * 2 + hh]) / (sDen[d * 2 + hh] + 1e-16f);
    }
    __syncthreads();

    const float bv = bias[tid];
    const int hh = tid >> 6;
    for (int n = 0; n < NNODE; n++) {
        float o = bv;
        int s0 = sStart[n], s1 = sStart[n + 1];
        for (int p = s0; p < s1; p++) {
            int e = sCsr[p];
            o = fmaf(sAlpha[e * 2 + hh], sH[sSrc[e] * CH + tid], o);
        }
        if (RELU) o = fmaxf(o, 0.f);
        out[(size_t)g * (NNODE * CH) + n * CH + tid] = o;
    }
}

// ---------------- tf32x3 tensor-core GEMM NT: C[M,N] = A[M,K]*W[N,K]^T + b0 + b1 ----------------
__device__ __forceinline__ uint32_t f2tf32(float f) {
    uint32_t u;
    asm("cvt.rna.tf32.f32 %0, %1;" : "=r"(u) : "f"(f));
    return u;
}

#define MMA_TF32(d, a, br0, br1)                                              \
    asm volatile(                                                             \
        "mma.sync.aligned.m16n8k8.row.col.f32.tf32.tf32.f32 "                 \
        "{%0,%1,%2,%3}, {%4,%5,%6,%7}, {%8,%9}, {%0,%1,%2,%3};"               \
        : "+f"(d[0]), "+f"(d[1]), "+f"(d[2]), "+f"(d[3])                      \
        : "r"(a[0]), "r"(a[1]), "r"(a[2]), "r"(a[3]), "r"(br0), "r"(br1))

__global__ __launch_bounds__(256) void tf32x3_gemm_nt(
    const float* __restrict__ A, const float* __restrict__ W,
    const float* __restrict__ bias0, const float* __restrict__ bias1,
    float* __restrict__ C, int M, int N, int K)
{
    __shared__ uint32_t sAhi[128][20], sAlo[128][20];
    __shared__ uint32_t sWhi[128][20], sWlo[128][20];

    const int tid = threadIdx.x;
    const int bm = blockIdx.y * 128, bn = blockIdx.x * 128;
    const int warp = tid >> 5, lane = tid & 31;
    const int wm = (warp >> 1) * 32, wn = (warp & 1) * 64;
    const int gid = lane >> 2, tig = lane & 3;

    float c[2][8][4];
#pragma unroll
    for (int m = 0; m < 2; m++)
#pragma unroll
        for (int j = 0; j < 8; j++)
#pragma unroll
            for (int q = 0; q < 4; q++) c[m][j][q] = 0.f;

    const int nkt = K >> 4;
    for (int kt = 0; kt < nkt; kt++) {
        const int k0g = kt << 4;
#pragma unroll
        for (int i = 0; i < 2; i++) {
            int idx = tid + i * 256;
            int r = idx >> 2, kq = (idx & 3) << 2;
            float4 av = *(const float4*)&A[(size_t)(bm + r) * K + k0g + kq];
            float4 wv = *(const float4*)&W[(size_t)(bn + r) * K + k0g + kq];
            float af[4] = {av.x, av.y, av.z, av.w};
            float wf[4] = {wv.x, wv.y, wv.z, wv.w};
#pragma unroll
            for (int q = 0; q < 4; q++) {
                uint32_t ahi = f2tf32(af[q]);
                sAhi[r][kq + q] = ahi;
                sAlo[r][kq + q] = f2tf32(af[q] - __uint_as_float(ahi));
                uint32_t whi = f2tf32(wf[q]);
                sWhi[r][kq + q] = whi;
                sWlo[r][kq + q] = f2tf32(wf[q] - __uint_as_float(whi));
            }
        }
        __syncthreads();

#pragma unroll
        for (int kk = 0; kk < 16; kk += 8) {
            uint32_t ahi[2][4], alo[2][4];
#pragma unroll
            for (int m = 0; m < 2; m++) {
                int rb = wm + m * 16;
                ahi[m][0] = sAhi[rb + gid][kk + tig];
                ahi[m][1] = sAhi[rb + gid + 8][kk + tig];
                ahi[m][2] = sAhi[rb + gid][kk + tig + 4];
                ahi[m][3] = sAhi[rb + gid + 8][kk + tig + 4];
                alo[m][0] = sAlo[rb + gid][kk + tig];
                alo[m][1] = sAlo[rb + gid + 8][kk + tig];
                alo[m][2] = sAlo[rb + gid][kk + tig + 4];
                alo[m][3] = sAlo[rb + gid + 8][kk + tig + 4];
            }
#pragma unroll
            for (int j = 0; j < 8; j++) {
                int nb = wn + j * 8 + gid;
                uint32_t bh0 = sWhi[nb][kk + tig], bh1 = sWhi[nb][kk + tig + 4];
                uint32_t bl0 = sWlo[nb][kk + tig], bl1 = sWlo[nb][kk + tig + 4];
#pragma unroll
                for (int m = 0; m < 2; m++) {
                    MMA_TF32(c[m][j], ahi[m], bh0, bh1);
                    MMA_TF32(c[m][j], ahi[m], bl0, bl1);
                    MMA_TF32(c[m][j], alo[m], bh0, bh1);
                }
            }
        }
        __syncthreads();
    }

#pragma unroll
    for (int m = 0; m < 2; m++) {
#pragma unroll
        for (int j = 0; j < 8; j++) {
            int row0 = bm + wm + m * 16 + gid;
            int col0 = bn + wn + j * 8 + 2 * tig;
            float bb0 = bias0 ? (bias0[col0] + bias1[col0]) : 0.f;
            float bb1 = bias0 ? (bias0[col0 + 1] + bias1[col0 + 1]) : 0.f;
            C[(size_t)row0 * N + col0]           = c[m][j][0] + bb0;
            C[(size_t)row0 * N + col0 + 1]       = c[m][j][1] + bb1;
            C[(size_t)(row0 + 8) * N + col0]     = c[m][j][2] + bb0;
            C[(size_t)(row0 + 8) * N + col0 + 1] = c[m][j][3] + bb1;
        }
    }
}

// ---------------- fp32 SGEMM NT (double-buffered) for the small K=128 projection ----------------
__global__ __launch_bounds__(256) void sgemm_nt(
    const float* __restrict__ A, const float* __restrict__ Bm,
    const float* __restrict__ b0, const float* __restrict__ b1,
    float* __restrict__ Cm, int M, int N, int K)
{
    __shared__ __align__(16) float sA[2][16][128];
    __shared__ __align__(16) float sB[2][16][128];
    const int tid = threadIdx.x;
    const int bm = blockIdx.y * 128, bn = blockIdx.x * 128;
    const int tx = tid & 15, ty = tid >> 4;
    const int lr0 = tid >> 2,         lk0 = tid & 3;
    const int lr1 = (tid + 256) >> 2, lk1 = (tid + 256) & 3;

    float acc[8][8] = {};
    float4 ra0, ra1, rb0, rb1;

    ra0 = *(const float4*)&A[(size_t)(bm + lr0) * K + lk0 * 4];
    ra1 = *(const float4*)&A[(size_t)(bm + lr1) * K + lk1 * 4];
    rb0 = *(const float4*)&Bm[(size_t)(bn + lr0) * K + lk0 * 4];
    rb1 = *(const float4*)&Bm[(size_t)(bn + lr1) * K + lk1 * 4];
    sA[0][lk0 * 4 + 0][lr0] = ra0.x; sA[0][lk0 * 4 + 1][lr0] = ra0.y;
    sA[0][lk0 * 4 + 2][lr0] = ra0.z; sA[0][lk0 * 4 + 3][lr0] = ra0.w;
    sA[0][lk1 * 4 + 0][lr1] = ra1.x; sA[0][lk1 * 4 + 1][lr1] = ra1.y;
    sA[0][lk1 * 4 + 2][lr1] = ra1.z; sA[0][lk1 * 4 + 3][lr1] = ra1.w;
    sB[0][lk0 * 4 + 0][lr0] = rb0.x; sB[0][lk0 * 4 + 1][lr0] = rb0.y;
    sB[0][lk0 * 4 + 2][lr0] = rb0.z; sB[0][lk0 * 4 + 3][lr0] = rb0.w;
    sB[0][lk1 * 4 + 0][lr1] = rb1.x; sB[0][lk1 * 4 + 1][lr1] = rb1.y;
    sB[0][lk1 * 4 + 2][lr1] = rb1.z; sB[0][lk1 * 4 + 3][lr1] = rb1.w;
    __syncthreads();

    const int nk = K >> 4;
    for (int kt = 0; kt < nk; kt++) {
        const int cur = kt & 1, nxt = cur ^ 1;
        const bool more = (kt + 1 < nk);
        if (more) {
            int k0 = (kt + 1) << 4;
            ra0 = *(const float4*)&A[(size_t)(bm + lr0) * K + k0 + lk0 * 4];
            ra1 = *(const float4*)&A[(size_t)(bm + lr1) * K + k0 + lk1 * 4];
            rb0 = *(const float4*)&Bm[(size_t)(bn + lr0) * K + k0 + lk0 * 4];
            rb1 = *(const float4*)&Bm[(size_t)(bn + lr1) * K + k0 + lk1 * 4];
        }
#pragma unroll
        for (int k = 0; k < 16; k++) {
            float a[8], b[8];
            *(float4*)&a[0] = *(const float4*)&sA[cur][k][ty * 8];
            *(float4*)&a[4] = *(const float4*)&sA[cur][k][ty * 8 + 4];
            *(float4*)&b[0] = *(const float4*)&sB[cur][k][tx * 8];
            *(float4*)&b[4] = *(const float4*)&sB[cur][k][tx * 8 + 4];
#pragma unroll
            for (int i = 0; i < 8; i++)
#pragma unroll
                for (int j = 0; j < 8; j++)
                    acc[i][j] = fmaf(a[i], b[j], acc[i][j]);
        }
        if (more) {
            sA[nxt][lk0 * 4 + 0][lr0] = ra0.x; sA[nxt][lk0 * 4 + 1][lr0] = ra0.y;
            sA[nxt][lk0 * 4 + 2][lr0] = ra0.z; sA[nxt][lk0 * 4 + 3][lr0] = ra0.w;
            sA[nxt][lk1 * 4 + 0][lr1] = ra1.x; sA[nxt][lk1 * 4 + 1][lr1] = ra1.y;
            sA[nxt][lk1 * 4 + 2][lr1] = ra1.z; sA[nxt][lk1 * 4 + 3][lr1] = ra1.w;
            sB[nxt][lk0 * 4 + 0][lr0] = rb0.x; sB[nxt][lk0 * 4 + 1][lr0] = rb0.y;
            sB[nxt][lk0 * 4 + 2][lr0] = rb0.z; sB[nxt][lk0 * 4 + 3][lr0] = rb0.w;
            sB[nxt][lk1 * 4 + 0][lr1] = rb1.x; sB[nxt][lk1 * 4 + 1][lr1] = rb1.y;
            sB[nxt][lk1 * 4 + 2][lr1] = rb1.z; sB[nxt][lk1 * 4 + 3][lr1] = rb1.w;
        }
        __syncthreads();
    }

    float bj[8];
#pragma unroll
    for (int j = 0; j < 8; j++) {
        int col = bn + tx * 8 + j;
        bj[j] = b0 ? (b0[col] + b1[col]) : 0.f;
    }
#pragma unroll
    for (int i = 0; i < 8; i++) {
        size_t row = (size_t)(bm + ty * 8 + i);
        float4 v0, v1;
        v0.x = acc[i][0] + bj[0]; v0.y = acc[i][1] + bj[1];
        v0.z = acc[i][2] + bj[2]; v0.w = acc[i][3] + bj[3];
        v1.x = acc[i][4] + bj[4]; v1.y = acc[i][5] + bj[5];
        v1.z = acc[i][6] + bj[6]; v1.w = acc[i][7] + bj[7];
        *(float4*)&Cm[row * N + bn + tx * 8]     = v0;
        *(float4*)&Cm[row * N + bn + tx * 8 + 4] = v1;
    }
}

// ---------------- LSTM recurrence: 4 batches/block, 64 blocks (R1, measured 3058 config) ----------------
__global__ __launch_bounds__(512) void lstm_kernel(
    const float* __restrict__ Xpre, const float* __restrict__ whhT,
    float* __restrict__ hs)
{
    __shared__ float sh[4][CH];
    __shared__ __align__(16) float4 sp[4][4][128];
    __shared__ __align__(16) float sg[4][G4];
    const int tid = threadIdx.x;
    const int b0 = blockIdx.x * 4;
    const int rq = tid & 127, kc = tid >> 7;
    const int ub = tid >> 7, uu = tid & 127;
    const float4* wT = (const float4*)whhT;

    sh[ub][uu] = 0.f;
    float c = 0.f;
    __syncthreads();

    for (int t = 0; t < TT; t++) {
        float4 a0 = {0,0,0,0}, a1 = {0,0,0,0}, a2 = {0,0,0,0}, a3 = {0,0,0,0};
        const int kbase = kc * 32;
#pragma unroll 8
        for (int kk = 0; kk < 32; kk++) {
            int k = kbase + kk;
            float4 w = wT[k * 128 + rq];
            float h0 = sh[0][k], h1 = sh[1][k], h2 = sh[2][k], h3 = sh[3][k];
            a0.x = fmaf(w.x, h0, a0.x); a0.y = fmaf(w.y, h0, a0.y);
            a0.z = fmaf(w.z, h0, a0.z); a0.w = fmaf(w.w, h0, a0.w);
            a1.x = fmaf(w.x, h1, a1.x); a1.y = fmaf(w.y, h1, a1.y);
            a1.z = fmaf(w.z, h1, a1.z); a1.w = fmaf(w.w, h1, a1.w);
            a2.x = fmaf(w.x, h2, a2.x); a2.y = fmaf(w.y, h2, a2.y);
            a2.z = fmaf(w.z, h2, a2.z); a2.w = fmaf(w.w, h2, a2.w);
            a3.x = fmaf(w.x, h3, a3.x); a3.y = fmaf(w.y, h3, a3.y);
            a3.z = fmaf(w.z, h3, a3.z); a3.w = fmaf(w.w, h3, a3.w);
        }
        sp[kc][0][rq] = a0; sp[kc][1][rq] = a1;
        sp[kc][2][rq] = a2; sp[kc][3][rq] = a3;
        __syncthreads();

        {
            int b = tid >> 7, r2 = tid & 127;
            float4 g = sp[0][b][r2], p1 = sp[1][b][r2], p2 = sp[2][b][r2], p3 = sp[3][b][r2];
            float4 xp = *(const float4*)&Xpre[((size_t)(b0 + b) * TT + t) * G4 + r2 * 4];
            g.x += p1.x + p2.x + p3.x + xp.x;
            g.y += p1.y + p2.y + p3.y + xp.y;
            g.z += p1.z + p2.z + p3.z + xp.z;
            g.w += p1.w + p2.w + p3.w + xp.w;
            *(float4*)&sg[b][r2 * 4] = g;
        }
        __syncthreads();

        {
            float gi = sg[ub][uu],        gf = sg[ub][128 + uu];
            float gg = sg[ub][256 + uu],  go = sg[ub][384 + uu];
            float fi = 1.f / (1.f + expf(-gi));
            float ff = 1.f / (1.f + expf(-gf));
            float fo = 1.f / (1.f + expf(-go));
            c = ff * c + fi * tanhf(gg);
            float h = fo * tanhf(c);
            sh[ub][uu] = h;
            hs[((size_t)(b0 + ub) * TT + t) * CH + uu] = h;
        }
        __syncthreads();
    }
}

// ---------------- attention + FC: one block per batch ----------------
__global__ __launch_bounds__(128) void attn_fc_kernel(
    const float* __restrict__ hs2, const float* __restrict__ attn_w,
    const float* __restrict__ attn_b, const float* __restrict__ fc_w,
    const float* __restrict__ fc_b, float* __restrict__ out)
{
    __shared__ float ssc[TT];
    __shared__ float sctx[CH];
    const int b = blockIdx.x, tid = threadIdx.x;

    if (tid < TT) {
        const float* hr = hs2 + ((size_t)b * TT + tid) * CH;
        float d = attn_b[0];
        for (int k = 0; k < CH; k++) d = fmaf(hr[k], attn_w[k], d);
        ssc[tid] = tanhf(d);
    }
    __syncthreads();
    if (tid == 0) {
        float m = -1e30f;
        for (int t = 0; t < TT; t++) m = fmaxf(m, ssc[t]);
        float s = 0.f;
        for (int t = 0; t < TT; t++) { float e = expf(ssc[t] - m); ssc[t] = e; s += e; }
        float inv = 1.f / s;
        for (int t = 0; t < TT; t++) ssc[t] *= inv;
    }
    __syncthreads();
    float cx = 0.f;
    for (int t = 0; t < TT; t++)
        cx = fmaf(ssc[t], hs2[((size_t)b * TT + t) * CH + tid], cx);
    sctx[tid] = cx;
    __syncthreads();
    if (tid < NCLS) {
        float o = fc_b[tid];
        for (int k = 0; k < CH; k++) o = fmaf(sctx[k], fc_w[tid * CH + k], o);
        out[b * NCLS + tid] = o;
    }
}

// ---------------- launch ----------------
extern "C" void kernel_launch(void* const* d_in, const int* in_sizes, int n_in,
                              void* d_out, int out_size) {
    const float* x     = (const float*)d_in[0];
    const int*   eidx  = (const int*)d_in[1];
    const float* gw[4], *gas[4], *gad[4], *gb[4];
    for (int i = 0; i < 4; i++) {
        gw[i]  = (const float*)d_in[2 + 4 * i];
        gas[i] = (const float*)d_in[3 + 4 * i];
        gad[i] = (const float*)d_in[4 + 4 * i];
        gb[i]  = (const float*)d_in[5 + 4 * i];
    }
    const float* wih0 = (const float*)d_in[18];
    const float* whh0 = (const float*)d_in[19];
    const float* bih0 = (const float*)d_in[20];
    const float* bhh0 = (const float*)d_in[21];
    const float* wih1 = (const float*)d_in[22];
    const float* whh1 = (const float*)d_in[23];
    const float* bih1 = (const float*)d_in[24];
    const float* bhh1 = (const float*)d_in[25];
    const float* attn_w = (const float*)d_in[26];
    const float* attn_b = (const float*)d_in[27];
    const float* fc_w   = (const float*)d_in[28];
    const float* fc_b   = (const float*)d_in[29];

    float *bufA, *bufB, *x0, *x1, *hs1, *hs2, *whhT0, *whhT1;
    cudaGetSymbolAddress((void**)&bufA,  g_bufA);
    cudaGetSymbolAddress((void**)&bufB,  g_bufB);
    cudaGetSymbolAddress((void**)&x0,    g_x0);
    cudaGetSymbolAddress((void**)&x1,    g_x1);
    cudaGetSymbolAddress((void**)&hs1,   g_hs1);
    cudaGetSymbolAddress((void**)&hs2,   g_hs2);
    cudaGetSymbolAddress((void**)&whhT0, g_whhT0);
    cudaGetSymbolAddress((void**)&whhT1, g_whhT1);

    setup_kernel<<<1, 32>>>(eidx);
    transpose_whh<<<256, 256>>>(whh0, whhT0);
    transpose_whh<<<256, 256>>>(whh1, whhT1);

    // fused GAT stack (measured-good R1 config)
    gat_kernel<3,   true ><<<GCNT, 128>>>(x,    gw[0], gas[0], gad[0], gb[0], bufA);
    gat_kernel<128, false><<<GCNT, 128>>>(bufA, gw[1], gas[1], gad[1], gb[1], bufB);
    gat_kernel<128, true ><<<GCNT, 128>>>(bufB, gw[2], gas[2], gad[2], gb[2], bufA);
    gat_kernel<128, false><<<GCNT, 128>>>(bufA, gw[3], gas[3], gad[3], gb[3], bufB);

    // LSTM stack: big input GEMM on tensor cores (tf32x3), rest as before
    tf32x3_gemm_nt<<<dim3(4, 128), 256>>>(bufB, wih0, bih0, bhh0, x0, GCNT, G4, LSTMIN);
    lstm_kernel<<<64, 512>>>(x0, whhT0, hs1);
    sgemm_nt<<<dim3(4, 128), 256>>>(hs1, wih1, bih1, bhh1, x1, GCNT, G4, CH);
    lstm_kernel<<<64, 512>>>(x1, whhT1, hs2);

    attn_fc_kernel<<<BB, 128>>>(hs2, attn_w, attn_b, fc_w, fc_b, (float*)d_out);
}

// round 12
// speedup vs baseline: 1.3405x; 1.1031x over previous
#include <cuda_runtime.h>
#include <cuda_bf16.h>
#include <cstdint>

#define GCNT   16384
#define NNODE  17
#define CH     128
#define NEDGE  81
#define TT     64
#define BB     256
#define G4     512
#define LSTMIN 2176
#define NCLS   10
#define MROWS  (GCNT * NNODE)   // 278528 = 2176 * 128

// ---------------- static device scratch ----------------
__device__ float g_bufA[(size_t)GCNT * NNODE * CH];
__device__ float g_bufB[(size_t)GCNT * NNODE * CH];
__device__ float g_x0[(size_t)GCNT * G4];
__device__ float g_x1[(size_t)GCNT * G4];
__device__ float g_hs1[(size_t)BB * TT * CH];
__device__ float g_hs2[(size_t)BB * TT * CH];
__device__ float g_whhT0[CH * G4];
__device__ float g_whhT1[CH * G4];
__device__ float g_wt[3 * CH * CH];
__device__ int g_src[NEDGE], g_dst[NEDGE], g_csr[NEDGE], g_start[NNODE + 1];

// ---------------- setup ----------------
__global__ void setup_kernel(const int* __restrict__ eidx) {
    if (threadIdx.x == 0) {
        for (int e = 0; e < 64; e++) { g_src[e] = eidx[e]; g_dst[e] = eidx[64 + e]; }
        for (int n = 0; n < NNODE; n++) { g_src[64 + n] = n; g_dst[64 + n] = n; }
        int pos = 0;
        for (int n = 0; n < NNODE; n++) {
            g_start[n] = pos;
            for (int e = 0; e < NEDGE; e++)
                if (g_dst[e] == n) g_csr[pos++] = e;
        }
        g_start[NNODE] = pos;
    }
}

__global__ void transpose_whh(const float* __restrict__ whh, float* __restrict__ out) {
    int i = blockIdx.x * 256 + threadIdx.x;
    if (i < G4 * CH) {
        int r = i / CH, k = i % CH;
        out[k * G4 + r] = whh[i];
    }
}

// W [128(k),128(n)] -> Wt [128(n),128(k)]
__global__ void transpose128(const float* __restrict__ W, float* __restrict__ Wt) {
    int i = blockIdx.x * 256 + threadIdx.x;   // 16384
    if (i < CH * CH) {
        int k = i >> 7, n = i & 127;
        Wt[n * CH + k] = W[i];
    }
}

// ---------------- fused GAT layer 0 (CIN=3): one block per graph ----------------
template <int CIN, bool RELU>
__global__ __launch_bounds__(128) void gat_kernel(
    const float* __restrict__ in, const float* __restrict__ W,
    const float* __restrict__ a_src, const float* __restrict__ a_dst,
    const float* __restrict__ bias, float* __restrict__ out)
{
    __shared__ __align__(16) float sIn[NNODE * CIN];
    __shared__ __align__(16) float sH[NNODE * CH];
    __shared__ float sAtt[2 * CH];
    __shared__ float sAS[NNODE * 2], sAD[NNODE * 2];
    __shared__ float sM[NNODE * 2], sDen[NNODE * 2];
    __shared__ float sAlpha[NEDGE * 2];
    __shared__ int sStart[NNODE + 1];
    __shared__ int sCsr[NEDGE], sSrc[NEDGE], sDst[NEDGE];

    const int g = blockIdx.x, tid = threadIdx.x;

    for (int i = tid; i < NNODE * CIN; i += 128)
        sIn[i] = in[(size_t)g * (NNODE * CIN) + i];
    sAtt[tid]      = a_src[tid];
    sAtt[CH + tid] = a_dst[tid];
    if (tid <= NNODE) sStart[tid] = g_start[tid];
    if (tid < NEDGE) { sCsr[tid] = g_csr[tid]; sSrc[tid] = g_src[tid]; sDst[tid] = g_dst[tid]; }
    __syncthreads();

    float acc[NNODE];
#pragma unroll
    for (int n = 0; n < NNODE; n++) acc[n] = 0.f;
#pragma unroll
    for (int k = 0; k < CIN; k++) {
        float w = W[k * CH + tid];
#pragma unroll
        for (int n = 0; n < NNODE; n++) acc[n] = fmaf(sIn[n * CIN + k], w, acc[n]);
    }
#pragma unroll
    for (int n = 0; n < NNODE; n++) sH[n * CH + tid] = acc[n];
    __syncthreads();

    if (tid < NNODE * 2) {
        int n = tid >> 1, hh = tid & 1;
        float s = 0.f, d = 0.f;
        const float* hrow = &sH[n * CH + hh * 64];
#pragma unroll 8
        for (int k = 0; k < 64; k++) {
            float hv = hrow[k];
            s = fmaf(hv, sAtt[hh * 64 + k], s);
            d = fmaf(hv, sAtt[CH + hh * 64 + k], d);
        }
        sAS[tid] = s; sAD[tid] = d;
    }
    __syncthreads();

    if (tid < NNODE * 2) {
        int n = tid >> 1, hh = tid & 1;
        float ad = sAD[n * 2 + hh];
        int s0 = sStart[n], s1 = sStart[n + 1];
        float m = -1e30f;
        for (int p = s0; p < s1; p++) {
            float v = sAS[sSrc[sCsr[p]] * 2 + hh] + ad;
            v = v > 0.f ? v : 0.2f * v;
            m = fmaxf(m, v);
        }
        float den = 0.f;
        for (int p = s0; p < s1; p++) {
            float v = sAS[sSrc[sCsr[p]] * 2 + hh] + ad;
            v = v > 0.f ? v : 0.2f * v;
            den += expf(v - m);
        }
        sM[tid] = m; sDen[tid] = den;
    }
    __syncthreads();

    for (int i = tid; i < NEDGE * 2; i += 128) {
        int e = i >> 1, hh = i & 1;
        int s = sSrc[e], d = sDst[e];
        float v = sAS[s * 2 + hh] + sAD[d * 2 + hh];
        v = v > 0.f ? v : 0.2f * v;
        sAlpha[i] = expf(v - sM[d * 2 + hh]) / (sDen[d * 2 + hh] + 1e-16f);
    }
    __syncthreads();

    const float bv = bias[tid];
    const int hh = tid >> 6;
    for (int n = 0; n < NNODE; n++) {
        float o = bv;
        int s0 = sStart[n], s1 = sStart[n + 1];
        for (int p = s0; p < s1; p++) {
            int e = sCsr[p];
            o = fmaf(sAlpha[e * 2 + hh], sH[sSrc[e] * CH + tid], o);
        }
        if (RELU) o = fmaxf(o, 0.f);
        out[(size_t)g * (NNODE * CH) + n * CH + tid] = o;
    }
}

// ---------------- GAT epilogue (after GEMM): one block per graph (R2-validated) ----------------
template <bool RELU>
__global__ __launch_bounds__(128) void gat_epilogue(
    const float* __restrict__ hbuf,    // [G,17,128] = in @ W
    const float* __restrict__ a_src, const float* __restrict__ a_dst,
    const float* __restrict__ bias, float* __restrict__ out)
{
    __shared__ __align__(16) float sH[NNODE * CH];
    __shared__ float sAtt[2 * CH];
    __shared__ float sAS[NNODE * 2], sAD[NNODE * 2];
    __shared__ float sM[NNODE * 2], sDen[NNODE * 2];
    __shared__ float sAlpha[NEDGE * 2];
    __shared__ int sStart[NNODE + 1];
    __shared__ int sCsr[NEDGE], sSrc[NEDGE], sDst[NEDGE];

    const int g = blockIdx.x, tid = threadIdx.x;
    const float4* src4 = (const float4*)(hbuf + (size_t)g * (NNODE * CH));
    float4* sH4 = (float4*)sH;
    for (int i = tid; i < NNODE * CH / 4; i += 128) sH4[i] = src4[i];
    sAtt[tid]      = a_src[tid];
    sAtt[CH + tid] = a_dst[tid];
    if (tid <= NNODE) sStart[tid] = g_start[tid];
    if (tid < NEDGE) { sCsr[tid] = g_csr[tid]; sSrc[tid] = g_src[tid]; sDst[tid] = g_dst[tid]; }
    __syncthreads();

    if (tid < NNODE * 2) {
        int n = tid >> 1, hh = tid & 1;
        float s = 0.f, d = 0.f;
        const float* hrow = &sH[n * CH + hh * 64];
#pragma unroll 8
        for (int k = 0; k < 64; k++) {
            float hv = hrow[k];
            s = fmaf(hv, sAtt[hh * 64 + k], s);
            d = fmaf(hv, sAtt[CH + hh * 64 + k], d);
        }
        sAS[tid] = s; sAD[tid] = d;
    }
    __syncthreads();

    if (tid < NNODE * 2) {
        int n = tid >> 1, hh = tid & 1;
        float ad = sAD[n * 2 + hh];
        int s0 = sStart[n], s1 = sStart[n + 1];
        float m = -1e30f;
        for (int p = s0; p < s1; p++) {
            float v = sAS[sSrc[sCsr[p]] * 2 + hh] + ad;
            v = v > 0.f ? v : 0.2f * v;
            m = fmaxf(m, v);
        }
        float den = 0.f;
        for (int p = s0; p < s1; p++) {
            float v = sAS[sSrc[sCsr[p]] * 2 + hh] + ad;
            v = v > 0.f ? v : 0.2f * v;
            den += expf(v - m);
        }
        sM[tid] = m; sDen[tid] = den;
    }
    __syncthreads();

    for (int i = tid; i < NEDGE * 2; i += 128) {
        int e = i >> 1, hh = i & 1;
        int s = sSrc[e], d = sDst[e];
        float v = sAS[s * 2 + hh] + sAD[d * 2 + hh];
        v = v > 0.f ? v : 0.2f * v;
        sAlpha[i] = expf(v - sM[d * 2 + hh]) / (sDen[d * 2 + hh] + 1e-16f);
    }
    __syncthreads();

    const float bv = bias[tid];
    const int hh = tid >> 6;
    for (int n = 0; n < NNODE; n++) {
        float o = bv;
        int s0 = sStart[n], s1 = sStart[n + 1];
        for (int p = s0; p < s1; p++) {
            int e = sCsr[p];
            o = fmaf(sAlpha[e * 2 + hh], sH[sSrc[e] * CH + tid], o);
        }
        if (RELU) o = fmaxf(o, 0.f);
        out[(size_t)g * (NNODE * CH) + n * CH + tid] = o;
    }
}

// ---------------- tf32x3 tensor-core GEMM NT: C[M,N] = A[M,K]*W[N,K]^T + b0 + b1 ----------------
__device__ __forceinline__ uint32_t f2tf32(float f) {
    uint32_t u;
    asm("cvt.rna.tf32.f32 %0, %1;" : "=r"(u) : "f"(f));
    return u;
}

#define MMA_TF32(d, a, br0, br1)                                              \
    asm volatile(                                                             \
        "mma.sync.aligned.m16n8k8.row.col.f32.tf32.tf32.f32 "                 \
        "{%0,%1,%2,%3}, {%4,%5,%6,%7}, {%8,%9}, {%0,%1,%2,%3};"               \
        : "+f"(d[0]), "+f"(d[1]), "+f"(d[2]), "+f"(d[3])                      \
        : "r"(a[0]), "r"(a[1]), "r"(a[2]), "r"(a[3]), "r"(br0), "r"(br1))

__global__ __launch_bounds__(256) void tf32x3_gemm_nt(
    const float* __restrict__ A, const float* __restrict__ W,
    const float* __restrict__ bias0, const float* __restrict__ bias1,
    float* __restrict__ C, int M, int N, int K)
{
    __shared__ uint32_t sAhi[128][20], sAlo[128][20];
    __shared__ uint32_t sWhi[128][20], sWlo[128][20];

    const int tid = threadIdx.x;
    const int bm = blockIdx.y * 128, bn = blockIdx.x * 128;
    const int warp = tid >> 5, lane = tid & 31;
    const int wm = (warp >> 1) * 32, wn = (warp & 1) * 64;
    const int gid = lane >> 2, tig = lane & 3;

    float c[2][8][4];
#pragma unroll
    for (int m = 0; m < 2; m++)
#pragma unroll
        for (int j = 0; j < 8; j++)
#pragma unroll
            for (int q = 0; q < 4; q++) c[m][j][q] = 0.f;

    const int nkt = K >> 4;
    for (int kt = 0; kt < nkt; kt++) {
        const int k0g = kt << 4;
#pragma unroll
        for (int i = 0; i < 2; i++) {
            int idx = tid + i * 256;
            int r = idx >> 2, kq = (idx & 3) << 2;
            float4 av = *(const float4*)&A[(size_t)(bm + r) * K + k0g + kq];
            float4 wv = *(const float4*)&W[(size_t)(bn + r) * K + k0g + kq];
            float af[4] = {av.x, av.y, av.z, av.w};
            float wf[4] = {wv.x, wv.y, wv.z, wv.w};
#pragma unroll
            for (int q = 0; q < 4; q++) {
                uint32_t ahi = f2tf32(af[q]);
                sAhi[r][kq + q] = ahi;
                sAlo[r][kq + q] = f2tf32(af[q] - __uint_as_float(ahi));
                uint32_t whi = f2tf32(wf[q]);
                sWhi[r][kq + q] = whi;
                sWlo[r][kq + q] = f2tf32(wf[q] - __uint_as_float(whi));
            }
        }
        __syncthreads();

#pragma unroll
        for (int kk = 0; kk < 16; kk += 8) {
            uint32_t ahi[2][4], alo[2][4];
#pragma unroll
            for (int m = 0; m < 2; m++) {
                int rb = wm + m * 16;
                ahi[m][0] = sAhi[rb + gid][kk + tig];
                ahi[m][1] = sAhi[rb + gid + 8][kk + tig];
                ahi[m][2] = sAhi[rb + gid][kk + tig + 4];
                ahi[m][3] = sAhi[rb + gid + 8][kk + tig + 4];
                alo[m][0] = sAlo[rb + gid][kk + tig];
                alo[m][1] = sAlo[rb + gid + 8][kk + tig];
                alo[m][2] = sAlo[rb + gid][kk + tig + 4];
                alo[m][3] = sAlo[rb + gid + 8][kk + tig + 4];
            }
#pragma unroll
            for (int j = 0; j < 8; j++) {
                int nb = wn + j * 8 + gid;
                uint32_t bh0 = sWhi[nb][kk + tig], bh1 = sWhi[nb][kk + tig + 4];
                uint32_t bl0 = sWlo[nb][kk + tig], bl1 = sWlo[nb][kk + tig + 4];
#pragma unroll
                for (int m = 0; m < 2; m++) {
                    MMA_TF32(c[m][j], ahi[m], bh0, bh1);
                    MMA_TF32(c[m][j], ahi[m], bl0, bl1);
                    MMA_TF32(c[m][j], alo[m], bh0, bh1);
                }
            }
        }
        __syncthreads();
    }

#pragma unroll
    for (int m = 0; m < 2; m++) {
#pragma unroll
        for (int j = 0; j < 8; j++) {
            int row0 = bm + wm + m * 16 + gid;
            int col0 = bn + wn + j * 8 + 2 * tig;
            float bb0 = bias0 ? (bias0[col0] + bias1[col0]) : 0.f;
            float bb1 = bias0 ? (bias0[col0 + 1] + bias1[col0 + 1]) : 0.f;
            C[(size_t)row0 * N + col0]           = c[m][j][0] + bb0;
            C[(size_t)row0 * N + col0 + 1]       = c[m][j][1] + bb1;
            C[(size_t)(row0 + 8) * N + col0]     = c[m][j][2] + bb0;
            C[(size_t)(row0 + 8) * N + col0 + 1] = c[m][j][3] + bb1;
        }
    }
}

// ---------------- fp32 SGEMM NT (double-buffered) for the small K=128 projection ----------------
__global__ __launch_bounds__(256) void sgemm_nt(
    const float* __restrict__ A, const float* __restrict__ Bm,
    const float* __restrict__ b0, const float* __restrict__ b1,
    float* __restrict__ Cm, int M, int N, int K)
{
    __shared__ __align__(16) float sA[2][16][128];
    __shared__ __align__(16) float sB[2][16][128];
    const int tid = threadIdx.x;
    const int bm = blockIdx.y * 128, bn = blockIdx.x * 128;
    const int tx = tid & 15, ty = tid >> 4;
    const int lr0 = tid >> 2,         lk0 = tid & 3;
    const int lr1 = (tid + 256) >> 2, lk1 = (tid + 256) & 3;

    float acc[8][8] = {};
    float4 ra0, ra1, rb0, rb1;

    ra0 = *(const float4*)&A[(size_t)(bm + lr0) * K + lk0 * 4];
    ra1 = *(const float4*)&A[(size_t)(bm + lr1) * K + lk1 * 4];
    rb0 = *(const float4*)&Bm[(size_t)(bn + lr0) * K + lk0 * 4];
    rb1 = *(const float4*)&Bm[(size_t)(bn + lr1) * K + lk1 * 4];
    sA[0][lk0 * 4 + 0][lr0] = ra0.x; sA[0][lk0 * 4 + 1][lr0] = ra0.y;
    sA[0][lk0 * 4 + 2][lr0] = ra0.z; sA[0][lk0 * 4 + 3][lr0] = ra0.w;
    sA[0][lk1 * 4 + 0][lr1] = ra1.x; sA[0][lk1 * 4 + 1][lr1] = ra1.y;
    sA[0][lk1 * 4 + 2][lr1] = ra1.z; sA[0][lk1 * 4 + 3][lr1] = ra1.w;
    sB[0][lk0 * 4 + 0][lr0] = rb0.x; sB[0][lk0 * 4 + 1][lr0] = rb0.y;
    sB[0][lk0 * 4 + 2][lr0] = rb0.z; sB[0][lk0 * 4 + 3][lr0] = rb0.w;
    sB[0][lk1 * 4 + 0][lr1] = rb1.x; sB[0][lk1 * 4 + 1][lr1] = rb1.y;
    sB[0][lk1 * 4 + 2][lr1] = rb1.z; sB[0][lk1 * 4 + 3][lr1] = rb1.w;
    __syncthreads();

    const int nk = K >> 4;
    for (int kt = 0; kt < nk; kt++) {
        const int cur = kt & 1, nxt = cur ^ 1;
        const bool more = (kt + 1 < nk);
        if (more) {
            int k0 = (kt + 1) << 4;
            ra0 = *(const float4*)&A[(size_t)(bm + lr0) * K + k0 + lk0 * 4];
            ra1 = *(const float4*)&A[(size_t)(bm + lr1) * K + k0 + lk1 * 4];
            rb0 = *(const float4*)&Bm[(size_t)(bn + lr0) * K + k0 + lk0 * 4];
            rb1 = *(const float4*)&Bm[(size_t)(bn + lr1) * K + k0 + lk1 * 4];
        }
#pragma unroll
        for (int k = 0; k < 16; k++) {
            float a[8], b[8];
            *(float4*)&a[0] = *(const float4*)&sA[cur][k][ty * 8];
            *(float4*)&a[4] = *(const float4*)&sA[cur][k][ty * 8 + 4];
            *(float4*)&b[0] = *(const float4*)&sB[cur][k][tx * 8];
            *(float4*)&b[4] = *(const float4*)&sB[cur][k][tx * 8 + 4];
#pragma unroll
            for (int i = 0; i < 8; i++)
#pragma unroll
                for (int j = 0; j < 8; j++)
                    acc[i][j] = fmaf(a[i], b[j], acc[i][j]);
        }
        if (more) {
            sA[nxt][lk0 * 4 + 0][lr0] = ra0.x; sA[nxt][lk0 * 4 + 1][lr0] = ra0.y;
            sA[nxt][lk0 * 4 + 2][lr0] = ra0.z; sA[nxt][lk0 * 4 + 3][lr0] = ra0.w;
            sA[nxt][lk1 * 4 + 0][lr1] = ra1.x; sA[nxt][lk1 * 4 + 1][lr1] = ra1.y;
            sA[nxt][lk1 * 4 + 2][lr1] = ra1.z; sA[nxt][lk1 * 4 + 3][lr1] = ra1.w;
            sB[nxt][lk0 * 4 + 0][lr0] = rb0.x; sB[nxt][lk0 * 4 + 1][lr0] = rb0.y;
            sB[nxt][lk0 * 4 + 2][lr0] = rb0.z; sB[nxt][lk0 * 4 + 3][lr0] = rb0.w;
            sB[nxt][lk1 * 4 + 0][lr1] = rb1.x; sB[nxt][lk1 * 4 + 1][lr1] = rb1.y;
            sB[nxt][lk1 * 4 + 2][lr1] = rb1.z; sB[nxt][lk1 * 4 + 3][lr1] = rb1.w;
        }
        __syncthreads();
    }

    float bj[8];
#pragma unroll
    for (int j = 0; j < 8; j++) {
        int col = bn + tx * 8 + j;
        bj[j] = b0 ? (b0[col] + b1[col]) : 0.f;
    }
#pragma unroll
    for (int i = 0; i < 8; i++) {
        size_t row = (size_t)(bm + ty * 8 + i);
        float4 v0, v1;
        v0.x = acc[i][0] + bj[0]; v0.y = acc[i][1] + bj[1];
        v0.z = acc[i][2] + bj[2]; v0.w = acc[i][3] + bj[3];
        v1.x = acc[i][4] + bj[4]; v1.y = acc[i][5] + bj[5];
        v1.z = acc[i][6] + bj[6]; v1.w = acc[i][7] + bj[7];
        *(float4*)&Cm[row * N + bn + tx * 8]     = v0;
        *(float4*)&Cm[row * N + bn + tx * 8 + 4] = v1;
    }
}

// ---------------- LSTM recurrence: 4 batches/block, 64 blocks (measured-good config) ----------------
__global__ __launch_bounds__(512) void lstm_kernel(
    const float* __restrict__ Xpre, const float* __restrict__ whhT,
    float* __restrict__ hs)
{
    __shared__ float sh[4][CH];
    __shared__ __align__(16) float4 sp[4][4][128];
    __shared__ __align__(16) float sg[4][G4];
    const int tid = threadIdx.x;
    const int b0 = blockIdx.x * 4;
    const int rq = tid & 127, kc = tid >> 7;
    const int ub = tid >> 7, uu = tid & 127;
    const float4* wT = (const float4*)whhT;

    sh[ub][uu] = 0.f;
    float c = 0.f;
    __syncthreads();

    for (int t = 0; t < TT; t++) {
        float4 a0 = {0,0,0,0}, a1 = {0,0,0,0}, a2 = {0,0,0,0}, a3 = {0,0,0,0};
        const int kbase = kc * 32;
#pragma unroll 8
        for (int kk = 0; kk < 32; kk++) {
            int k = kbase + kk;
            float4 w = wT[k * 128 + rq];
            float h0 = sh[0][k], h1 = sh[1][k], h2 = sh[2][k], h3 = sh[3][k];
            a0.x = fmaf(w.x, h0, a0.x); a0.y = fmaf(w.y, h0, a0.y);
            a0.z = fmaf(w.z, h0, a0.z); a0.w = fmaf(w.w, h0, a0.w);
            a1.x = fmaf(w.x, h1, a1.x); a1.y = fmaf(w.y, h1, a1.y);
            a1.z = fmaf(w.z, h1, a1.z); a1.w = fmaf(w.w, h1, a1.w);
            a2.x = fmaf(w.x, h2, a2.x); a2.y = fmaf(w.y, h2, a2.y);
            a2.z = fmaf(w.z, h2, a2.z); a2.w = fmaf(w.w, h2, a2.w);
            a3.x = fmaf(w.x, h3, a3.x); a3.y = fmaf(w.y, h3, a3.y);
            a3.z = fmaf(w.z, h3, a3.z); a3.w = fmaf(w.w, h3, a3.w);
        }
        sp[kc][0][rq] = a0; sp[kc][1][rq] = a1;
        sp[kc][2][rq] = a2; sp[kc][3][rq] = a3;
        __syncthreads();

        {
            int b = tid >> 7, r2 = tid & 127;
            float4 g = sp[0][b][r2], p1 = sp[1][b][r2], p2 = sp[2][b][r2], p3 = sp[3][b][r2];
            float4 xp = *(const float4*)&Xpre[((size_t)(b0 + b) * TT + t) * G4 + r2 * 4];
            g.x += p1.x + p2.x + p3.x + xp.x;
            g.y += p1.y + p2.y + p3.y + xp.y;
            g.z += p1.z + p2.z + p3.z + xp.z;
            g.w += p1.w + p2.w + p3.w + xp.w;
            *(float4*)&sg[b][r2 * 4] = g;
        }
        __syncthreads();

        {
            float gi = sg[ub][uu],        gf = sg[ub][128 + uu];
            float gg = sg[ub][256 + uu],  go = sg[ub][384 + uu];
            float fi = 1.f / (1.f + expf(-gi));
            float ff = 1.f / (1.f + expf(-gf));
            float fo = 1.f / (1.f + expf(-go));
            c = ff * c + fi * tanhf(gg);
            float h = fo * tanhf(c);
            sh[ub][uu] = h;
            hs[((size_t)(b0 + ub) * TT + t) * CH + uu] = h;
        }
        __syncthreads();
    }
}

// ---------------- attention + FC: one block per batch ----------------
__global__ __launch_bounds__(128) void attn_fc_kernel(
    const float* __restrict__ hs2, const float* __restrict__ attn_w,
    const float* __restrict__ attn_b, const float* __restrict__ fc_w,
    const float* __restrict__ fc_b, float* __restrict__ out)
{
    __shared__ float ssc[TT];
    __shared__ float sctx[CH];
    const int b = blockIdx.x, tid = threadIdx.x;

    if (tid < TT) {
        const float* hr = hs2 + ((size_t)b * TT + tid) * CH;
        float d = attn_b[0];
        for (int k = 0; k < CH; k++) d = fmaf(hr[k], attn_w[k], d);
        ssc[tid] = tanhf(d);
    }
    __syncthreads();
    if (tid == 0) {
        float m = -1e30f;
        for (int t = 0; t < TT; t++) m = fmaxf(m, ssc[t]);
        float s = 0.f;
        for (int t = 0; t < TT; t++) { float e = expf(ssc[t] - m); ssc[t] = e; s += e; }
        float inv = 1.f / s;
        for (int t = 0; t < TT; t++) ssc[t] *= inv;
    }
    __syncthreads();
    float cx = 0.f;
    for (int t = 0; t < TT; t++)
        cx = fmaf(ssc[t], hs2[((size_t)b * TT + t) * CH + tid], cx);
    sctx[tid] = cx;
    __syncthreads();
    if (tid < NCLS) {
        float o = fc_b[tid];
        for (int k = 0; k < CH; k++) o = fmaf(sctx[k], fc_w[tid * CH + k], o);
        out[b * NCLS + tid] = o;
    }
}

// ---------------- launch ----------------
extern "C" void kernel_launch(void* const* d_in, const int* in_sizes, int n_in,
                              void* d_out, int out_size) {
    const float* x     = (const float*)d_in[0];
    const int*   eidx  = (const int*)d_in[1];
    const float* gw[4], *gas[4], *gad[4], *gb[4];
    for (int i = 0; i < 4; i++) {
        gw[i]  = (const float*)d_in[2 + 4 * i];
        gas[i] = (const float*)d_in[3 + 4 * i];
        gad[i] = (const float*)d_in[4 + 4 * i];
        gb[i]  = (const float*)d_in[5 + 4 * i];
    }
    const float* wih0 = (const float*)d_in[18];
    const float* whh0 = (const float*)d_in[19];
    const float* bih0 = (const float*)d_in[20];
    const float* bhh0 = (const float*)d_in[21];
    const float* wih1 = (const float*)d_in[22];
    const float* whh1 = (const float*)d_in[23];
    const float* bih1 = (const float*)d_in[24];
    const float* bhh1 = (const float*)d_in[25];
    const float* attn_w = (const float*)d_in[26];
    const float* attn_b = (const float*)d_in[27];
    const float* fc_w   = (const float*)d_in[28];
    const float* fc_b   = (const float*)d_in[29];

    float *bufA, *bufB, *x0, *x1, *hs1, *hs2, *whhT0, *whhT1, *wt;
    cudaGetSymbolAddress((void**)&bufA,  g_bufA);
    cudaGetSymbolAddress((void**)&bufB,  g_bufB);
    cudaGetSymbolAddress((void**)&x0,    g_x0);
    cudaGetSymbolAddress((void**)&x1,    g_x1);
    cudaGetSymbolAddress((void**)&hs1,   g_hs1);
    cudaGetSymbolAddress((void**)&hs2,   g_hs2);
    cudaGetSymbolAddress((void**)&whhT0, g_whhT0);
    cudaGetSymbolAddress((void**)&whhT1, g_whhT1);
    cudaGetSymbolAddress((void**)&wt,    g_wt);

    setup_kernel<<<1, 32>>>(eidx);
    transpose_whh<<<256, 256>>>(whh0, whhT0);
    transpose_whh<<<256, 256>>>(whh1, whhT1);
    transpose128<<<64, 256>>>(gw[1], wt + 0 * CH * CH);
    transpose128<<<64, 256>>>(gw[2], wt + 1 * CH * CH);
    transpose128<<<64, 256>>>(gw[3], wt + 2 * CH * CH);

    // layer 0 fused (CIN=3, relu)
    gat_kernel<3, true><<<GCNT, 128>>>(x, gw[0], gas[0], gad[0], gb[0], bufA);

    // layers 1..3: tf32x3 tensor-core GEMM (h = in @ W) + validated epilogue
    tf32x3_gemm_nt<<<dim3(1, MROWS / 128), 256>>>(bufA, wt + 0 * CH * CH, nullptr, nullptr, bufB, MROWS, CH, CH);
    gat_epilogue<false><<<GCNT, 128>>>(bufB, gas[1], gad[1], gb[1], bufA);
    tf32x3_gemm_nt<<<dim3(1, MROWS / 128), 256>>>(bufA, wt + 1 * CH * CH, nullptr, nullptr, bufB, MROWS, CH, CH);
    gat_epilogue<true><<<GCNT, 128>>>(bufB, gas[2], gad[2], gb[2], bufA);
    tf32x3_gemm_nt<<<dim3(1, MROWS / 128), 256>>>(bufA, wt + 2 * CH * CH, nullptr, nullptr, bufB, MROWS, CH, CH);
    gat_epilogue<false><<<GCNT, 128>>>(bufB, gas[3], gad[3], gb[3], bufA);

    // LSTM stack: big input GEMM on tensor cores (tf32x3), rest as before
    tf32x3_gemm_nt<<<dim3(4, 128), 256>>>(bufA, wih0, bih0, bhh0, x0, GCNT, G4, LSTMIN);
    lstm_kernel<<<64, 512>>>(x0, whhT0, hs1);
    sgemm_nt<<<dim3(4, 128), 256>>>(hs1, wih1, bih1, bhh1, x1, GCNT, G4, CH);
    lstm_kernel<<<64, 512>>>(x1, whhT1, hs2);

    attn_fc_kernel<<<BB, 128>>>(hs2, attn_w, attn_b, fc_w, fc_b, (float*)d_out);
}